// round 13
// baseline (speedup 1.0000x reference)
#include <cuda_runtime.h>
#include <cuda_bf16.h>
#include <math.h>

#define SEQ 4096
#define NF 2048
#define HID 1024
#define GATES 4096
#define TAGS 10
#define START_TAG 8
#define STOP_TAG 9
#define NCTA 64        // CTAs per direction (scan)
#define NHC 16         // h-elements per CTA (64*16 = 1024 exactly)
#define NJR 5          // W_hh col-chunks in registers (j=0..4); j=5..7 in SMEM
#define NSC 3          // SMEM col-chunks
#define SENT 0x7fc0deadu   // qNaN sentinel; finite h can never equal this

// packed f32x2 FMA: d = a*b + d (per 32-bit half, exact fp32)
#define FFMA2(d, a, b) asm("fma.rn.f32x2 %0, %1, %2, %3;" \
                           : "=l"(d) : "l"(a), "l"(b), "l"(d))
#define PACKF2(out, lo, hi) asm("mov.b64 %0, {%1, %2};" : "=l"(out) : "f"(lo), "f"(hi))
#define PACKU2(out, lo, hi) asm("mov.b64 %0, {%1, %2};" : "=l"(out) : "r"(lo), "r"(hi))
#define UNPACKF2(lo, hi, in) asm("mov.b64 {%0, %1}, %2;" : "=f"(lo), "=f"(hi) : "l"(in))

// ---------------- scratch (module-static; no runtime allocation) ----------------
__device__ float g_xp[2][SEQ][GATES];   // precomputed input projections
__device__ float g_h[2][SEQ][HID];      // hidden states (sentinel-coded each launch)
__device__ float g_feats[SEQ][TAGS];

// sentinel-fill g_h (runs every launch -> graph-replay safe)
__global__ void init_kernel() {
    uint4 s; s.x = SENT; s.y = SENT; s.z = SENT; s.w = SENT;
    uint4* p = (uint4*)g_h;
    const int n = 2 * SEQ * HID / 4;
    for (int i = blockIdx.x * blockDim.x + threadIdx.x; i < n; i += gridDim.x * blockDim.x)
        p[i] = s;
}

__global__ void dummy_kernelA() {}      // keep ncu capture slot on lstm_scan (4th launch)

// ---------------- Kernel 1: xp = X @ W_ih^T + b  (both directions) ----------------
__global__ void __launch_bounds__(256, 2) gemm_xp(const float* __restrict__ X,
                                                  const float* __restrict__ Wf,
                                                  const float* __restrict__ bf,
                                                  const float* __restrict__ Wb,
                                                  const float* __restrict__ bb)
{
    const int dir = blockIdx.z;
    const float* __restrict__ Wg   = dir ? Wb : Wf;
    const float* __restrict__ bias = dir ? bb : bf;

    __shared__ __align__(16) float As[8][128];
    __shared__ __align__(16) float Bs[8][128];

    const int tid = threadIdx.x;
    const int tx = tid & 15, ty = tid >> 4;
    const int bm = blockIdx.y * 128;
    const int bn = blockIdx.x * 128;

    unsigned long long acc2[8][4];
#pragma unroll
    for (int i = 0; i < 8; i++)
#pragma unroll
        for (int j = 0; j < 4; j++) acc2[i][j] = 0ull;

    const int lr = tid >> 1;
    const int lc = (tid & 1) * 4;
    const float* Ap = X  + (size_t)(bm + lr) * NF + lc;
    const float* Bp = Wg + (size_t)(bn + lr) * NF + lc;

    float4 a = *(const float4*)Ap;
    float4 b = *(const float4*)Bp;

    for (int k0 = 0; k0 < NF; k0 += 8) {
        __syncthreads();
        As[lc + 0][lr] = a.x; As[lc + 1][lr] = a.y; As[lc + 2][lr] = a.z; As[lc + 3][lr] = a.w;
        Bs[lc + 0][lr] = b.x; Bs[lc + 1][lr] = b.y; Bs[lc + 2][lr] = b.z; Bs[lc + 3][lr] = b.w;
        __syncthreads();
        if (k0 + 8 < NF) {
            a = *(const float4*)(Ap + k0 + 8);
            b = *(const float4*)(Bp + k0 + 8);
        }
#pragma unroll
        for (int k = 0; k < 8; k++) {
            float4 a0 = *(const float4*)&As[k][ty * 4];
            float4 a1 = *(const float4*)&As[k][64 + ty * 4];
            ulonglong2 b0 = *(const ulonglong2*)&Bs[k][tx * 4];
            ulonglong2 b1 = *(const ulonglong2*)&Bs[k][64 + tx * 4];
            float av[8] = {a0.x, a0.y, a0.z, a0.w, a1.x, a1.y, a1.z, a1.w};
#pragma unroll
            for (int i = 0; i < 8; i++) {
                unsigned long long ad;
                PACKF2(ad, av[i], av[i]);
                FFMA2(acc2[i][0], ad, b0.x);
                FFMA2(acc2[i][1], ad, b0.y);
                FFMA2(acc2[i][2], ad, b1.x);
                FFMA2(acc2[i][3], ad, b1.y);
            }
        }
    }

#pragma unroll
    for (int i = 0; i < 8; i++) {
        const int row = bm + ((i < 4) ? (ty * 4 + i) : (64 + ty * 4 + i - 4));
#pragma unroll
        for (int jp = 0; jp < 4; jp++) {
            const int col = bn + ((jp < 2) ? (tx * 4 + jp * 2) : (64 + tx * 4 + (jp - 2) * 2));
            float lo, hi;
            UNPACKF2(lo, hi, acc2[i][jp]);
            g_xp[dir][row][col + 0] = lo + bias[col + 0];
            g_xp[dir][row][col + 1] = hi + bias[col + 1];
        }
    }
}

// ---------------- Kernel 2: barrier-free persistent BiLSTM scan ----------------
// Warp-closed: each warp owns 2 h-elements x 4 gates (8 rows). No __syncthreads,
// no flags in the step loop: consumers poll sentinel-coded h words directly.
__device__ __forceinline__ float sigf(float x) { return 1.0f / (1.0f + expf(-x)); }

__global__ void __launch_bounds__(256, 1) lstm_scan(const float* __restrict__ Whf,
                                                    const float* __restrict__ Whb)
{
    extern __shared__ __align__(16) float Wsh[];   // [64 rows][NSC*128] cols 640..1023

    const int dir = (blockIdx.x >= NCTA) ? 1 : 0;
    const int ci  = blockIdx.x - dir * NCTA;
    const float* __restrict__ W = dir ? Whb : Whf;
    const int hstart = ci * NHC;

    const int tid  = threadIdx.x;
    const int lane = tid & 31;
    const int warp = tid >> 5;
    const int ebase = hstart + 2 * warp;           // this warp's first h-element

    // rows r=0..7: element (r>>2), gate (r&3)  ->  xp/gate row index
    int rowg[8];
#pragma unroll
    for (int r = 0; r < 8; r++) rowg[r] = (r & 3) * HID + ebase + (r >> 2);

    // ---- register-resident W_hh chunks (cols 0..639): 160 regs ----
    unsigned long long wreg[8][NJR][2];
#pragma unroll
    for (int r = 0; r < 8; r++) {
        const float* wrow = W + (size_t)rowg[r] * HID;
#pragma unroll
        for (int j = 0; j < NJR; j++) {
            float4 v = *(const float4*)&wrow[j * 128 + lane * 4];
            PACKF2(wreg[r][j][0], v.x, v.y);
            PACKF2(wreg[r][j][1], v.z, v.w);
        }
    }
    // ---- cooperative SMEM load of cols 640..1023 (all 64 CTA rows) ----
    for (int idx = tid; idx < 64 * NSC * 32; idx += 256) {
        const int q  = idx / (NSC * 32);           // CTA row 0..63
        const int c4 = idx % (NSC * 32);           // float4 within row's smem cols
        const int wq = q >> 3, rq = q & 7;
        const int rg = (rq & 3) * HID + hstart + 2 * wq + (rq >> 2);
        float4 v = *(const float4*)&W[(size_t)rg * HID + NJR * 128 + c4 * 4];
        *(float4*)&Wsh[q * (NSC * 128) + c4 * 4] = v;
    }

    // lane r (<8) carries xp for its row; prefetched one step ahead
    const int myrow = (lane & 3) * HID + ebase + (lane >> 2);
    float xpcur = 0.f;
    if (lane < 8) xpcur = g_xp[dir][dir ? (SEQ - 1) : 0][myrow];
    float creg = 0.f;                               // lanes 0,1: cell state
    __syncthreads();                                // one-time: Wsh ready

    for (int t = 0; t < SEQ; ++t) {
        const int time = dir ? (SEQ - 1 - t) : t;

        // prefetch next step's xp (independent of h)
        float xpn = 0.f;
        if (lane < 8 && t + 1 < SEQ)
            xpn = g_xp[dir][dir ? (time - 1) : (time + 1)][myrow];

        // h_{prev}: volatile poll on sentinel-coded data (data IS the flag)
        uint4 u[8];
        if (t > 0) {
            const int pt = dir ? (time + 1) : (time - 1);
            const unsigned* hp = (const unsigned*)&g_h[dir][pt][0];
            unsigned pending = 0xffu;
#pragma unroll
            for (int j = 0; j < 8; j++) {
                asm volatile("ld.volatile.global.v4.u32 {%0,%1,%2,%3}, [%4];"
                             : "=r"(u[j].x), "=r"(u[j].y), "=r"(u[j].z), "=r"(u[j].w)
                             : "l"(hp + j * 128 + lane * 4) : "memory");
                if (u[j].x != SENT && u[j].y != SENT && u[j].z != SENT && u[j].w != SENT)
                    pending &= ~(1u << j);
            }
            while (__any_sync(0xffffffffu, pending != 0u)) {
                __nanosleep(40);
#pragma unroll
                for (int j = 0; j < 8; j++) {
                    if (pending & (1u << j)) {
                        asm volatile("ld.volatile.global.v4.u32 {%0,%1,%2,%3}, [%4];"
                                     : "=r"(u[j].x), "=r"(u[j].y), "=r"(u[j].z), "=r"(u[j].w)
                                     : "l"(hp + j * 128 + lane * 4) : "memory");
                        if (u[j].x != SENT && u[j].y != SENT && u[j].z != SENT && u[j].w != SENT)
                            pending &= ~(1u << j);
                    }
                }
            }
        } else {
#pragma unroll
            for (int j = 0; j < 8; j++) { u[j].x = 0u; u[j].y = 0u; u[j].z = 0u; u[j].w = 0u; }
        }

        // dot products: register chunks then SMEM chunks, f32x2 accumulation
        unsigned long long acc[8];
#pragma unroll
        for (int r = 0; r < 8; r++) acc[r] = 0ull;
#pragma unroll
        for (int j = 0; j < NJR; j++) {
            unsigned long long hx, hy;
            PACKU2(hx, u[j].x, u[j].y);
            PACKU2(hy, u[j].z, u[j].w);
#pragma unroll
            for (int r = 0; r < 8; r++) {
                FFMA2(acc[r], wreg[r][j][0], hx);
                FFMA2(acc[r], wreg[r][j][1], hy);
            }
        }
#pragma unroll
        for (int j = NJR; j < 8; j++) {
            unsigned long long hx, hy;
            PACKU2(hx, u[j].x, u[j].y);
            PACKU2(hy, u[j].z, u[j].w);
#pragma unroll
            for (int r = 0; r < 8; r++) {
                ulonglong2 w2 = *(const ulonglong2*)
                    &Wsh[(warp * 8 + r) * (NSC * 128) + (j - NJR) * 128 + lane * 4];
                FFMA2(acc[r], w2.x, hx);
                FFMA2(acc[r], w2.y, hy);
            }
        }

        // reduce: lane r captures row r's pre-activation
        float pre = 0.f;
#pragma unroll
        for (int r = 0; r < 8; r++) {
            float lo, hi;
            UNPACKF2(lo, hi, acc[r]);
            float s = lo + hi;
#pragma unroll
            for (int off = 16; off; off >>= 1) s += __shfl_xor_sync(0xffffffffu, s, off);
            if (lane == r) pre = s + xpcur;
        }

        // lanes 0..7: activation (gate 2 -> tanh, else sigmoid)
        float act = 0.f;
        if (lane < 8) act = ((lane & 3) == 2) ? tanhf(pre) : sigf(pre);

        // gather 4 gates for element (lane&1); lanes 0,1 update state + store h
        const int e4 = (lane & 1) * 4;
        const float ai = __shfl_sync(0xffffffffu, act, e4 + 0);
        const float af = __shfl_sync(0xffffffffu, act, e4 + 1);
        const float ag = __shfl_sync(0xffffffffu, act, e4 + 2);
        const float ao = __shfl_sync(0xffffffffu, act, e4 + 3);
        if (lane < 2) {
            const float c = af * creg + ai * ag;
            const float h = ao * tanhf(c);
            creg = c;
            asm volatile("st.volatile.global.b32 [%0], %1;"
                         :: "l"(&g_h[dir][time][ebase + lane]), "r"(__float_as_uint(h))
                         : "memory");
        }
        xpcur = xpn;
    }
}

// ---------------- Kernel 3: feats[t] = W_lin @ concat(h_f[t], h_b[t]) + b_lin ----------------
__global__ void __launch_bounds__(320) feats_kernel(const float* __restrict__ Wl,
                                                    const float* __restrict__ bl)
{
    const int t = blockIdx.x;
    const int warp = threadIdx.x >> 5;   // = tag, exactly 10 warps
    const int lane = threadIdx.x & 31;
    const float4* hf = (const float4*)&g_h[0][t][0];
    const float4* hb = (const float4*)&g_h[1][t][0];
    const float4* w0 = (const float4*)&Wl[warp * (2 * HID)];
    const float4* w1 = (const float4*)&Wl[warp * (2 * HID) + HID];
    float s = 0.f;
#pragma unroll 4
    for (int k = lane; k < HID / 4; k += 32) {
        float4 h4 = hf[k], v4 = w0[k];
        s = fmaf(h4.x, v4.x, s); s = fmaf(h4.y, v4.y, s);
        s = fmaf(h4.z, v4.z, s); s = fmaf(h4.w, v4.w, s);
    }
#pragma unroll 4
    for (int k = lane; k < HID / 4; k += 32) {
        float4 h4 = hb[k], v4 = w1[k];
        s = fmaf(h4.x, v4.x, s); s = fmaf(h4.y, v4.y, s);
        s = fmaf(h4.z, v4.z, s); s = fmaf(h4.w, v4.w, s);
    }
#pragma unroll
    for (int off = 16; off; off >>= 1) s += __shfl_xor_sync(0xffffffffu, s, off);
    if (lane == 0) g_feats[t][warp] = s + bl[warp];
}

// ---------------- Kernel 4: Viterbi (sequential, warp-shuffle recurrence) ----------------
__global__ void __launch_bounds__(256) viterbi_kernel(const float* __restrict__ trans,
                                                      float* __restrict__ out, int out_size)
{
    extern __shared__ float sh[];
    float* sfeats = sh;                                     // SEQ*TAGS floats
    unsigned char* bps = (unsigned char*)(sh + SEQ * TAGS); // SEQ*TAGS bytes

    const int tid = threadIdx.x;
    const float* gf = &g_feats[0][0];
    for (int i = tid; i < SEQ * TAGS; i += blockDim.x) sfeats[i] = gf[i];
    __syncthreads();

    if (tid < 32) {
        const int j = tid;
        float tt[TAGS];
#pragma unroll
        for (int i = 0; i < TAGS; i++) tt[i] = (j < TAGS) ? trans[j * TAGS + i] : 0.f;

        float fv = (j == START_TAG) ? 0.f : -10000.f;
        for (int t = 0; t < SEQ; ++t) {
            float best = -3.4e38f; int arg = 0;
#pragma unroll
            for (int i = 0; i < TAGS; i++) {
                const float v = __shfl_sync(0xffffffffu, fv, i);
                const float sc = v + tt[i];
                if (sc > best) { best = sc; arg = i; }
            }
            const float feat = (j < TAGS) ? sfeats[t * TAGS + j] : 0.f;
            fv = best + feat;
            if (j < TAGS) bps[t * TAGS + j] = (unsigned char)arg;
        }

        float term = (j < TAGS) ? (fv + trans[STOP_TAG * TAGS + j]) : -3.4e38f;
        float bscore = -3.4e38f; int btag = 0;
#pragma unroll
        for (int i = 0; i < TAGS; i++) {
            const float v = __shfl_sync(0xffffffffu, term, i);
            if (v > bscore) { bscore = v; btag = i; }
        }

        if (j == 0) {
            out[0] = bscore;
            int tag = btag;
            for (int t = SEQ - 1; t >= 0; --t) {
                if (1 + t < out_size) out[1 + t] = (float)tag;
                tag = bps[t * TAGS + tag];
            }
        }
    }
}

// ---------------- launch ----------------
extern "C" void kernel_launch(void* const* d_in, const int* in_sizes, int n_in,
                              void* d_out, int out_size)
{
    const float* sentence = (const float*)d_in[0];
    const float* W_ih_f   = (const float*)d_in[1];
    const float* W_hh_f   = (const float*)d_in[2];
    const float* b_f      = (const float*)d_in[3];
    const float* W_ih_b   = (const float*)d_in[4];
    const float* W_hh_b   = (const float*)d_in[5];
    const float* b_b      = (const float*)d_in[6];
    const float* W_lin    = (const float*)d_in[7];
    const float* b_lin    = (const float*)d_in[8];
    const float* trans    = (const float*)d_in[9];

    const int scan_smem = 64 * NSC * 128 * (int)sizeof(float);   // 98304 B
    cudaFuncSetAttribute(lstm_scan, cudaFuncAttributeMaxDynamicSharedMemorySize, scan_smem);
    cudaFuncSetAttribute(viterbi_kernel, cudaFuncAttributeMaxDynamicSharedMemorySize,
                         SEQ * TAGS * 5);                        // 204800 B

    // lstm_scan stays the 4th launch (ncu capture slot)
    dim3 gg(GATES / 128, SEQ / 128, 2);
    gemm_xp<<<gg, 256>>>(sentence, W_ih_f, b_f, W_ih_b, b_b);

    init_kernel<<<1024, 256>>>();       // sentinel-fill g_h (every launch/replay)
    dummy_kernelA<<<1, 32>>>();

    lstm_scan<<<2 * NCTA, 256, scan_smem>>>(W_hh_f, W_hh_b);

    feats_kernel<<<SEQ, 320>>>(W_lin, b_lin);

    viterbi_kernel<<<1, 256, SEQ * TAGS * 5>>>(trans, (float*)d_out, out_size);
}

// round 14
// speedup vs baseline: 2.8477x; 2.8477x over previous
#include <cuda_runtime.h>
#include <cuda_bf16.h>
#include <math.h>

#define SEQ 4096
#define NF 2048
#define HID 1024
#define GATES 4096
#define TAGS 10
#define START_TAG 8
#define STOP_TAG 9
#define NCTA 74        // CTAs per direction in the scan
#define NHC 14         // h-elements owned per CTA (74*14 >= 1024)
#define ROWS 56        // 4 gates * NHC weight rows per CTA
#define NJR 6          // weight col-chunks in registers (j=0..5); j=6,7 in SMEM

// packed f32x2 FMA: d = a*b + d (per 32-bit half, exact fp32)
#define FFMA2(d, a, b) asm("fma.rn.f32x2 %0, %1, %2, %3;" \
                           : "=l"(d) : "l"(a), "l"(b), "l"(d))
#define PACKF2(out, lo, hi) asm("mov.b64 %0, {%1, %2};" : "=l"(out) : "f"(lo), "f"(hi))
#define UNPACKF2(lo, hi, in) asm("mov.b64 {%0, %1}, %2;" : "=f"(lo), "=f"(hi) : "l"(in))

// fast transcendentals: MUFU-based (~1e-6 abs err; LSTM gates contract error)
__device__ __forceinline__ float fsig(float x) {
    return __fdividef(1.0f, 1.0f + __expf(-x));
}
__device__ __forceinline__ float ftanh(float x) {
    return 1.0f - __fdividef(2.0f, __expf(2.0f * x) + 1.0f);
}

// ---------------- scratch (module-static; no runtime allocation) ----------------
__device__ float g_xp[2][SEQ][GATES];   // precomputed input projections
__device__ float g_h[2][SEQ][HID];      // per-direction hidden states
__device__ float g_feats[SEQ][TAGS];
__device__ __align__(256) unsigned g_cnt[128];   // [0]=dir0, [64]=dir1 (separate lines)

__global__ void init_kernel() {
    if (threadIdx.x < 128) g_cnt[threadIdx.x] = 0u;
}

__global__ void dummy_kernelA() {}      // keep ncu capture slot on lstm_scan (4th launch)

// ---------------- Kernel 1: xp = X @ W_ih^T + b  (both directions) ----------------
// EXACT structure of the 12.83ms-measured kernel (single-buffer, prefetch).
__global__ void __launch_bounds__(256, 2) gemm_xp(const float* __restrict__ X,
                                                  const float* __restrict__ Wf,
                                                  const float* __restrict__ bf,
                                                  const float* __restrict__ Wb,
                                                  const float* __restrict__ bb)
{
    const int dir = blockIdx.z;
    const float* __restrict__ Wg   = dir ? Wb : Wf;
    const float* __restrict__ bias = dir ? bb : bf;

    __shared__ __align__(16) float As[8][128];
    __shared__ __align__(16) float Bs[8][128];

    const int tid = threadIdx.x;
    const int tx = tid & 15, ty = tid >> 4;
    const int bm = blockIdx.y * 128;
    const int bn = blockIdx.x * 128;

    unsigned long long acc2[8][4];
#pragma unroll
    for (int i = 0; i < 8; i++)
#pragma unroll
        for (int j = 0; j < 4; j++) acc2[i][j] = 0ull;

    const int lr = tid >> 1;
    const int lc = (tid & 1) * 4;
    const float* Ap = X  + (size_t)(bm + lr) * NF + lc;
    const float* Bp = Wg + (size_t)(bn + lr) * NF + lc;

    float4 a = *(const float4*)Ap;
    float4 b = *(const float4*)Bp;

    for (int k0 = 0; k0 < NF; k0 += 8) {
        __syncthreads();
        As[lc + 0][lr] = a.x; As[lc + 1][lr] = a.y; As[lc + 2][lr] = a.z; As[lc + 3][lr] = a.w;
        Bs[lc + 0][lr] = b.x; Bs[lc + 1][lr] = b.y; Bs[lc + 2][lr] = b.z; Bs[lc + 3][lr] = b.w;
        __syncthreads();
        if (k0 + 8 < NF) {                       // prefetch next tile under compute
            a = *(const float4*)(Ap + k0 + 8);
            b = *(const float4*)(Bp + k0 + 8);
        }
#pragma unroll
        for (int k = 0; k < 8; k++) {
            float4 a0 = *(const float4*)&As[k][ty * 4];
            float4 a1 = *(const float4*)&As[k][64 + ty * 4];
            ulonglong2 b0 = *(const ulonglong2*)&Bs[k][tx * 4];
            ulonglong2 b1 = *(const ulonglong2*)&Bs[k][64 + tx * 4];
            float av[8] = {a0.x, a0.y, a0.z, a0.w, a1.x, a1.y, a1.z, a1.w};
#pragma unroll
            for (int i = 0; i < 8; i++) {
                unsigned long long ad;
                PACKF2(ad, av[i], av[i]);
                FFMA2(acc2[i][0], ad, b0.x);
                FFMA2(acc2[i][1], ad, b0.y);
                FFMA2(acc2[i][2], ad, b1.x);
                FFMA2(acc2[i][3], ad, b1.y);
            }
        }
    }

#pragma unroll
    for (int i = 0; i < 8; i++) {
        const int row = bm + ((i < 4) ? (ty * 4 + i) : (64 + ty * 4 + i - 4));
#pragma unroll
        for (int jp = 0; jp < 4; jp++) {
            const int col = bn + ((jp < 2) ? (tx * 4 + jp * 2) : (64 + tx * 4 + (jp - 2) * 2));
            float lo, hi;
            UNPACKF2(lo, hi, acc2[i][jp]);
            g_xp[dir][row][col + 0] = lo + bias[col + 0];
            g_xp[dir][row][col + 1] = hi + bias[col + 1];
        }
    }
}

// ---------------- Kernel 2: persistent bidirectional LSTM scan ----------------
// R5 champion structure; changes: fast transcendentals, parallel activations,
// warp-local tail barrier, relaxed poll + single acquire, lane-held xp.
__global__ void __launch_bounds__(256, 1) lstm_scan(const float* __restrict__ Whf,
                                                    const float* __restrict__ Whb)
{
    extern __shared__ __align__(16) float Wsh[];  // [ROWS][256] cols 768..1023
    __shared__ float asum[64];                    // post-activation gate values

    const int dir = (blockIdx.x >= NCTA) ? 1 : 0;
    const int ci  = blockIdx.x - dir * NCTA;
    const float* __restrict__ W = dir ? Whb : Whf;
    unsigned* const cnt = &g_cnt[dir * 64];
    const int hstart = ci * NHC;

    const int tid  = threadIdx.x;
    const int lane = tid & 31;
    const int warp = tid >> 5;
    const int rbase = warp * 7;
    const bool tanh_warp = (warp == 4 || warp == 5);   // rows 28..41 = gate g

    // ---- register-resident weight chunks (cols 0..767): 168 regs ----
    unsigned long long wreg[7][NJR][2];
#pragma unroll
    for (int rr = 0; rr < 7; rr++) {
        const int r = rbase + rr;
        const int gate = r / NHC, lh = r % NHC;
        int hg = hstart + lh; if (hg >= HID) hg = HID - 1;  // clamp; values unused
        const float* wrow = W + (size_t)(gate * HID + hg) * HID;
#pragma unroll
        for (int j = 0; j < NJR; j++) {
            float4 v = *(const float4*)&wrow[j * 128 + lane * 4];
            PACKF2(wreg[rr][j][0], v.x, v.y);
            PACKF2(wreg[rr][j][1], v.z, v.w);
        }
    }
    // ---- cooperative SMEM load of cols 768..1023 ----
    for (int idx = tid; idx < ROWS * 64; idx += 256) {
        const int r = idx >> 6, c4 = idx & 63;
        const int gate = r / NHC, lh = r % NHC;
        int hg = hstart + lh; if (hg >= HID) hg = HID - 1;
        float4 v = *(const float4*)&W[(size_t)(gate * HID + hg) * HID + 768 + c4 * 4];
        *(float4*)&Wsh[r * 256 + c4 * 4] = v;
    }

    // lane rr (<7) holds xp for row rbase+rr of the current step
    int myrow = 0;
    float xpcur = 0.f;
    if (lane < 7) {
        const int r = rbase + lane;
        const int gate = r / NHC;
        int hg = hstart + r % NHC; if (hg >= HID) hg = HID - 1;
        myrow = gate * HID + hg;
        xpcur = g_xp[dir][dir ? (SEQ - 1) : 0][myrow];
    }
    float creg = 0.f;
    __syncthreads();

    for (int t = 0; t < SEQ; ++t) {
        const int time = dir ? (SEQ - 1 - t) : t;

        // prefetch next step's xp BEFORE the poll (latency fully hidden)
        float xpn = 0.f;
        if (lane < 7 && t + 1 < SEQ)
            xpn = g_xp[dir][dir ? (time - 1) : (time + 1)][myrow];

        // grid sync: tid0 relaxed-polls, ONE acquire on detect, block barrier
        if (t > 0) {
            if (tid == 0) {
                const unsigned target = (unsigned)(NCTA * t);
                unsigned v;
                do {
                    asm volatile("ld.relaxed.gpu.global.u32 %0, [%1];"
                                 : "=r"(v) : "l"(cnt) : "memory");
                } while (v < target);
                asm volatile("ld.acquire.gpu.global.u32 %0, [%1];"
                             : "=r"(v) : "l"(cnt) : "memory");
            }
            __syncthreads();
        }

        // load h_{prev} as packed f32x2 pairs (MLP=8)
        ulonglong2 hv2[8];
        if (t > 0) {
            const int pt = dir ? (time + 1) : (time - 1);
            const ulonglong2* hp = (const ulonglong2*)&g_h[dir][pt][0];
#pragma unroll
            for (int j = 0; j < 8; j++) hv2[j] = hp[j * 32 + lane];
        } else {
#pragma unroll
            for (int j = 0; j < 8; j++) { hv2[j].x = 0ull; hv2[j].y = 0ull; }
        }

        // dot products: register chunks then SMEM chunks, f32x2 accumulation
        unsigned long long acc2[7];
#pragma unroll
        for (int rr = 0; rr < 7; rr++) acc2[rr] = 0ull;
#pragma unroll
        for (int j = 0; j < NJR; j++) {
#pragma unroll
            for (int rr = 0; rr < 7; rr++) {
                FFMA2(acc2[rr], wreg[rr][j][0], hv2[j].x);
                FFMA2(acc2[rr], wreg[rr][j][1], hv2[j].y);
            }
        }
#pragma unroll
        for (int j = NJR; j < 8; j++) {
#pragma unroll
            for (int rr = 0; rr < 7; rr++) {
                ulonglong2 w2 = *(const ulonglong2*)&Wsh[(rbase + rr) * 256 + (j - NJR) * 128 + lane * 4];
                FFMA2(acc2[rr], w2.x, hv2[j].x);
                FFMA2(acc2[rr], w2.y, hv2[j].y);
            }
        }

        // reduce; lane rr captures row rbase+rr's pre-activation
        float pre = 0.f;
#pragma unroll
        for (int rr = 0; rr < 7; rr++) {
            float lo, hi;
            UNPACKF2(lo, hi, acc2[rr]);
            float s = lo + hi;
#pragma unroll
            for (int off = 16; off; off >>= 1) s += __shfl_xor_sync(0xffffffffu, s, off);
            if (lane == rr) pre = s + xpcur;
        }

        // parallel activations: lanes 0..6 of EVERY warp (uniform gate per warp)
        if (lane < 7) asum[rbase + lane] = tanh_warp ? ftanh(pre) : fsig(pre);
        xpcur = xpn;
        __syncthreads();        // asum published

        // warp 0 only: cheap combine, h store, release (no CTA-wide tail barrier)
        if (warp == 0) {
            if (tid < NHC) {
                const int hg = hstart + tid;
                const float ai = asum[tid];
                const float af = asum[NHC + tid];
                const float ag = asum[2 * NHC + tid];
                const float ao = asum[3 * NHC + tid];
                const float c = af * creg + ai * ag;
                const float h = ao * ftanh(c);
                creg = c;
                if (hg < HID) g_h[dir][time][hg] = h;
            }
            __syncwarp();
            if (lane == 0) {
                unsigned one = 1u;
                asm volatile("red.release.gpu.global.add.u32 [%0], %1;"
                             :: "l"(cnt), "r"(one) : "memory");
            }
        }
    }
}

// ---------------- Kernel 3: feats[t] = W_lin @ concat(h_f[t], h_b[t]) + b_lin ----------------
__global__ void __launch_bounds__(320) feats_kernel(const float* __restrict__ Wl,
                                                    const float* __restrict__ bl)
{
    const int t = blockIdx.x;
    const int warp = threadIdx.x >> 5;   // = tag, exactly 10 warps
    const int lane = threadIdx.x & 31;
    const float4* hf = (const float4*)&g_h[0][t][0];
    const float4* hb = (const float4*)&g_h[1][t][0];
    const float4* w0 = (const float4*)&Wl[warp * (2 * HID)];
    const float4* w1 = (const float4*)&Wl[warp * (2 * HID) + HID];
    float s = 0.f;
#pragma unroll 4
    for (int k = lane; k < HID / 4; k += 32) {
        float4 h4 = hf[k], v4 = w0[k];
        s = fmaf(h4.x, v4.x, s); s = fmaf(h4.y, v4.y, s);
        s = fmaf(h4.z, v4.z, s); s = fmaf(h4.w, v4.w, s);
    }
#pragma unroll 4
    for (int k = lane; k < HID / 4; k += 32) {
        float4 h4 = hb[k], v4 = w1[k];
        s = fmaf(h4.x, v4.x, s); s = fmaf(h4.y, v4.y, s);
        s = fmaf(h4.z, v4.z, s); s = fmaf(h4.w, v4.w, s);
    }
#pragma unroll
    for (int off = 16; off; off >>= 1) s += __shfl_xor_sync(0xffffffffu, s, off);
    if (lane == 0) g_feats[t][warp] = s + bl[warp];
}

// ---------------- Kernel 4: Viterbi (sequential, warp-shuffle recurrence) ----------------
__global__ void __launch_bounds__(256) viterbi_kernel(const float* __restrict__ trans,
                                                      float* __restrict__ out, int out_size)
{
    extern __shared__ float sh[];
    float* sfeats = sh;                                     // SEQ*TAGS floats
    unsigned char* bps = (unsigned char*)(sh + SEQ * TAGS); // SEQ*TAGS bytes

    const int tid = threadIdx.x;
    const float* gf = &g_feats[0][0];
    for (int i = tid; i < SEQ * TAGS; i += blockDim.x) sfeats[i] = gf[i];
    __syncthreads();

    if (tid < 32) {
        const int j = tid;      // lane j holds fv[j]
        float tt[TAGS];
#pragma unroll
        for (int i = 0; i < TAGS; i++) tt[i] = (j < TAGS) ? trans[j * TAGS + i] : 0.f;

        float fv = (j == START_TAG) ? 0.f : -10000.f;
        for (int t = 0; t < SEQ; ++t) {
            float best = -3.4e38f; int arg = 0;
#pragma unroll
            for (int i = 0; i < TAGS; i++) {
                const float v = __shfl_sync(0xffffffffu, fv, i);
                const float sc = v + tt[i];
                if (sc > best) { best = sc; arg = i; }   // strict > keeps first argmax
            }
            const float feat = (j < TAGS) ? sfeats[t * TAGS + j] : 0.f;
            fv = best + feat;
            if (j < TAGS) bps[t * TAGS + j] = (unsigned char)arg;
        }

        float term = (j < TAGS) ? (fv + trans[STOP_TAG * TAGS + j]) : -3.4e38f;
        float bscore = -3.4e38f; int btag = 0;
#pragma unroll
        for (int i = 0; i < TAGS; i++) {
            const float v = __shfl_sync(0xffffffffu, term, i);
            if (v > bscore) { bscore = v; btag = i; }
        }

        if (j == 0) {
            out[0] = bscore;
            int tag = btag;
            for (int t = SEQ - 1; t >= 0; --t) {
                if (1 + t < out_size) out[1 + t] = (float)tag;
                tag = bps[t * TAGS + tag];
            }
        }
    }
}

// ---------------- launch ----------------
extern "C" void kernel_launch(void* const* d_in, const int* in_sizes, int n_in,
                              void* d_out, int out_size)
{
    const float* sentence = (const float*)d_in[0];
    const float* W_ih_f   = (const float*)d_in[1];
    const float* W_hh_f   = (const float*)d_in[2];
    const float* b_f      = (const float*)d_in[3];
    const float* W_ih_b   = (const float*)d_in[4];
    const float* W_hh_b   = (const float*)d_in[5];
    const float* b_b      = (const float*)d_in[6];
    const float* W_lin    = (const float*)d_in[7];
    const float* b_lin    = (const float*)d_in[8];
    const float* trans    = (const float*)d_in[9];

    const int scan_smem = ROWS * 256 * (int)sizeof(float);   // 57344 B
    cudaFuncSetAttribute(lstm_scan, cudaFuncAttributeMaxDynamicSharedMemorySize, scan_smem);
    cudaFuncSetAttribute(viterbi_kernel, cudaFuncAttributeMaxDynamicSharedMemorySize,
                         SEQ * TAGS * 5);                    // 204800 B

    // lstm_scan stays the 4th launch (ncu capture slot)
    dim3 gg(GATES / 128, SEQ / 128, 2);
    gemm_xp<<<gg, 256>>>(sentence, W_ih_f, b_f, W_ih_b, b_b);

    init_kernel<<<1, 128>>>();
    dummy_kernelA<<<1, 32>>>();

    lstm_scan<<<2 * NCTA, 256, scan_smem>>>(W_hh_f, W_hh_b);

    feats_kernel<<<SEQ, 320>>>(W_lin, b_lin);

    viterbi_kernel<<<1, 256, SEQ * TAGS * 5>>>(trans, (float*)d_out, out_size);
}